// round 16
// baseline (speedup 1.0000x reference)
#include <cuda_runtime.h>
#include <cstdint>

// Problem constants
#define NB 8
#define NW 32
#define NX 64
#define NY 64
#define NT 40
#define NKZ 8          // retained T modes (M3)
#define NK 24          // retained X/Y modes (2*M1 = 2*M2)
#define XYT 163840     // 64*64*40
#define YTD 2560       // 64*40
#define NMODE 4608     // 24*24*8
#define WPL 4718592    // 4*32*32*12*12*8  (spectral weights per layer)

// ---- scratch (device globals; no allocations anywhere) ----
static __device__ float  g_bufA[(size_t)NB*NW*XYT];                 // 168 MB
static __device__ float  g_bufB[(size_t)NB*NW*XYT];                 // 168 MB
static __device__ float2 g_ft1[(size_t)NB*NW*NX*NY*NKZ];            // 67 MB
static __device__ float2 g_ft2[(size_t)NB*NW*NX*NK*NKZ];            // 25 MB
static __device__ float2 g_modes [(size_t)NB*NW*NMODE];             // 9.4 MB
static __device__ float2 g_modes2[(size_t)NB*NW*NMODE];             // 9.4 MB
static __device__ float2 g_wt[(size_t)3*WPL];                       // 113 MB
static __device__ float2 g_tw_t[NKZ*NT];    // forward T twiddles  e^{-2pi i k t/40}
static __device__ float2 g_itw_t[NKZ*NT];   // inverse T twiddles  c_k/(XYT) * e^{+2pi i k t/40}
static __device__ float2 g_tw_yx[NK*64];    // forward X/Y twiddles e^{-2pi i kv y/64}

__device__ __forceinline__ void cfma(float2& a, float2 b, float2 c){
  a.x = fmaf(b.x, c.x, fmaf(-b.y, c.y, a.x));
  a.y = fmaf(b.x, c.y, fmaf( b.y, c.x, a.y));
}
__device__ __forceinline__ void cfma_cj(float2& a, float2 b, float2 c){ // a += b*conj(c)
  a.x = fmaf(b.x, c.x, fmaf( b.y, c.y, a.x));
  a.y = fmaf(b.y, c.x, fmaf(-b.x, c.y, a.y));
}
__device__ __forceinline__ float gelu_f(float z){
  return 0.5f*z*(1.0f + erff(z*0.7071067811865476f));
}

// ---- twiddle tables ----
__global__ void k_init_tw(){
  int tid = threadIdx.x;
  for (int i = tid; i < NKZ*NT; i += blockDim.x){
    int k = i / NT, t = i % NT;
    float s, c; sincospif(-(float)(k*t)/20.0f, &s, &c);   // -2pi k t / 40
    g_tw_t[i] = make_float2(c, s);
    float sc = ((k==0) ? 1.0f : 2.0f) * (1.0f/163840.0f);
    float s2, c2; sincospif((float)(k*t)/20.0f, &s2, &c2);
    g_itw_t[i] = make_float2(sc*c2, sc*s2);
  }
  for (int i = tid; i < NK*64; i += blockDim.x){
    int j = i / 64, y = i % 64;
    int kv = (j < 12) ? j : j + 40;                        // 0..11, 52..63
    float s, c; sincospif(-(float)(kv*y)/32.0f, &s, &c);   // -2pi kv y / 64
    g_tw_yx[i] = make_float2(c, s);
  }
}

// ---- transpose spectral weights via 32x32 shared tile ----
__global__ void __launch_bounds__(256) k_prep_w_t(const float* __restrict__ wr,
                                                  const float* __restrict__ wi, int L){
  __shared__ float2 s[32][33];
  int m0  = blockIdx.x * 32;
  int io0 = blockIdx.y * 32;
  int r   = blockIdx.z;
  int tid = threadIdx.x;
  {
    int mt = tid & 31, iot0 = tid >> 5;
    const size_t inbase = (size_t)r * 1024 * 1152;
    #pragma unroll
    for (int u = 0; u < 4; u++){
      int io = io0 + iot0 + u*8;
      size_t off = inbase + (size_t)io*1152 + m0 + mt;
      s[iot0 + u*8][mt] = make_float2(wr[off], wi[off]);
    }
  }
  __syncthreads();
  {
    int iot = tid & 31, mt0 = tid >> 5;
    int rbase = (r & 1) * 2304 + ((r >> 1) & 1) * 96;
    float2* dst = g_wt + (size_t)L*WPL;
    #pragma unroll
    for (int u = 0; u < 4; u++){
      int m  = m0 + mt0 + u*8;
      int m1 = m / 96, rem = m % 96;
      int mode = rbase + m1*192 + rem;
      dst[(size_t)mode*1024 + io0 + iot] = s[iot][mt0 + u*8];
    }
  }
}

// ---- fc0: lift [B,X,Y,T,5] -> v [B,W,X,Y,T] ----
__global__ void k_fc0(const float* __restrict__ h, const float* __restrict__ xin,
                      const float* __restrict__ w, const float* __restrict__ b){
  int p = blockIdx.x * blockDim.x + threadIdx.x;
  if (p >= NB*XYT) return;
  int bb = p / XYT, rem = p % XYT;
  float in5[5];
  in5[0] = h[(size_t)p*2];   in5[1] = h[(size_t)p*2+1];
  in5[2] = xin[(size_t)p*3]; in5[3] = xin[(size_t)p*3+1]; in5[4] = xin[(size_t)p*3+2];
  float* o = g_bufA + (size_t)bb*NW*XYT + rem;
  #pragma unroll 4
  for (int c = 0; c < NW; c++){
    float v = b[c];
    #pragma unroll
    for (int f = 0; f < 5; f++) v = fmaf(in5[f], w[f*NW + c], v);
    o[(size_t)c*XYT] = v;
  }
}

// ---- forward partial DFT over T, radix 8x5 ----
__global__ void __launch_bounds__(128) k_fwdT_r(int dir){
  __shared__ float  s[2*NY*41];
  __shared__ float2 stw40[NT];
  const float* vin = dir ? g_bufB : g_bufA;
  int bcx0 = blockIdx.x * 2;
  const float* src = vin + (size_t)bcx0*YTD;
  int tid = threadIdx.x;
  for (int i = tid; i < 2*YTD; i += 128){
    int sl = i / YTD, r = i % YTD;
    s[sl*2624 + (r/NT)*41 + (r%NT)] = src[i];
  }
  if (tid < NT) stw40[tid] = g_tw_t[40 + tid];
  __syncthreads();
  int sl = tid >> 6, y = tid & 63;
  const float* row = s + sl*2624 + y*41;
  const float C = 0.70710678118654752f;
  float g0[5], g4[5], g1r[5], g1i[5], g2r[5], g2i[5], g3r[5], g3i[5];
  #pragma unroll
  for (int b = 0; b < 5; b++){
    float a0 = row[b], a1 = row[5+b], a2 = row[10+b], a3 = row[15+b];
    float a4 = row[20+b], a5 = row[25+b], a6 = row[30+b], a7 = row[35+b];
    float s0 = a0+a4, s1 = a1+a5, s2 = a2+a6, s3 = a3+a7;
    float d0 = a0-a4, d1 = a1-a5, d2 = a2-a6, d3 = a3-a7;
    g0[b] = (s0+s2) + (s1+s3);
    g4[b] = (s0+s2) - (s1+s3);
    g2r[b] = s0-s2;  g2i[b] = s3-s1;
    float t1 = C*(d1-d3), t2 = C*(d1+d3);
    g1r[b] = d0+t1;  g1i[b] = -d2 - t2;
    g3r[b] = d0-t1;  g3i[b] =  d2 - t2;
  }
  float Xr[8], Xi[8];
  Xr[0] = g0[0]+g0[1]+g0[2]+g0[3]+g0[4];  Xi[0] = 0.f;
  #pragma unroll
  for (int k = 1; k < 8; k++){ Xr[k] = 0.f; Xi[k] = 0.f; }
  #pragma unroll
  for (int b = 0; b < 5; b++){
    float2 tw;
    tw = stw40[1*b];
    Xr[1] = fmaf(tw.x, g1r[b], fmaf(-tw.y, g1i[b], Xr[1]));
    Xi[1] = fmaf(tw.x, g1i[b], fmaf( tw.y, g1r[b], Xi[1]));
    tw = stw40[2*b];
    Xr[2] = fmaf(tw.x, g2r[b], fmaf(-tw.y, g2i[b], Xr[2]));
    Xi[2] = fmaf(tw.x, g2i[b], fmaf( tw.y, g2r[b], Xi[2]));
    tw = stw40[3*b];
    Xr[3] = fmaf(tw.x, g3r[b], fmaf(-tw.y, g3i[b], Xr[3]));
    Xi[3] = fmaf(tw.x, g3i[b], fmaf( tw.y, g3r[b], Xi[3]));
    tw = stw40[4*b];
    Xr[4] = fmaf(tw.x, g4[b], Xr[4]);
    Xi[4] = fmaf(tw.y, g4[b], Xi[4]);
    tw = stw40[5*b];
    Xr[5] = fmaf(tw.x, g3r[b], fmaf( tw.y, g3i[b], Xr[5]));
    Xi[5] = fmaf(tw.x, -g3i[b], fmaf( tw.y, g3r[b], Xi[5]));
    tw = stw40[6*b];
    Xr[6] = fmaf(tw.x, g2r[b], fmaf( tw.y, g2i[b], Xr[6]));
    Xi[6] = fmaf(tw.x, -g2i[b], fmaf( tw.y, g2r[b], Xi[6]));
    tw = stw40[7*b];
    Xr[7] = fmaf(tw.x, g1r[b], fmaf( tw.y, g1i[b], Xr[7]));
    Xi[7] = fmaf(tw.x, -g1i[b], fmaf( tw.y, g1r[b], Xi[7]));
  }
  float2* dst = g_ft1 + ((size_t)(bcx0+sl)*NY + y)*NKZ;
  #pragma unroll
  for (int k = 0; k < NKZ; k++) dst[k] = make_float2(Xr[k], Xi[k]);
}

// ---- forward partial DFT over Y: warp-broadcast twiddles, 8 slices, 384 thr ----
__global__ void __launch_bounds__(384) k_fwdY(){
  __shared__ float2 sv[8*512];      // 32 KB  [s][y*8+k]
  __shared__ float2 stw[NK*64];     // 12 KB
  int bcx0 = blockIdx.x * 8;
  int tid = threadIdx.x;
  for (int i = tid; i < 4096; i += 384) sv[i] = g_ft1[(size_t)bcx0*512 + i];
  for (int i = tid; i < NK*64; i += 384) stw[i] = g_tw_yx[i];
  __syncthreads();
  int w = tid >> 5;                  // 12 warps
  int wj = w % 6;                    // j-group of 4
  int half = w / 6;                  // slice half
  int lane = tid & 31;
  int s = half*4 + (lane >> 3), k = lane & 7;
  const float2* svp = sv + s*512 + k;
  const float2* twp = stw + wj*256;
  float2 a0 = make_float2(0.f,0.f), a1 = a0, a2 = a0, a3 = a0;
  #pragma unroll 4
  for (int y = 0; y < 64; y++){
    float2 v = svp[y*8];
    cfma(a0, v, twp[y]);
    cfma(a1, v, twp[64 + y]);
    cfma(a2, v, twp[128 + y]);
    cfma(a3, v, twp[192 + y]);
  }
  float2* dst = g_ft2 + (size_t)(bcx0 + s)*192 + k;
  dst[(wj*4 + 0)*8] = a0;
  dst[(wj*4 + 1)*8] = a1;
  dst[(wj*4 + 2)*8] = a2;
  dst[(wj*4 + 3)*8] = a3;
}

// ---- forward partial DFT over X: stream x once, 6 j1 per block ----
__global__ void __launch_bounds__(192) k_fwdX(){
  __shared__ float2 stw[6*64];
  int bc = blockIdx.x >> 2;
  int jg = (blockIdx.x & 3) * 6;
  int tid = threadIdx.x;
  for (int i = tid; i < 6*64; i += 192) stw[i] = g_tw_yx[jg*64 + i];
  __syncthreads();
  const float2* src = g_ft2 + (size_t)bc*NX*192 + tid;
  float2 acc[6];
  #pragma unroll
  for (int j = 0; j < 6; j++) acc[j] = make_float2(0.f, 0.f);
  #pragma unroll 4
  for (int x = 0; x < 64; x++){
    float2 v = src[(size_t)x*192];
    #pragma unroll
    for (int j = 0; j < 6; j++) cfma(acc[j], v, stw[j*64 + x]);
  }
  float2* dst = g_modes + (size_t)bc*NMODE + (size_t)jg*192 + tid;
  #pragma unroll
  for (int j = 0; j < 6; j++) dst[(size_t)j*192] = acc[j];
}

// ---- channel mix per mode ----
__global__ void k_mix(int L){
  __shared__ float2 s_in[256];
  __shared__ float2 s_w[1024];
  int m = blockIdx.x;
  int tid = threadIdx.x;
  s_in[tid] = g_modes[(size_t)tid*NMODE + m];
  const float2* wt = g_wt + (size_t)L*WPL + (size_t)m*1024;
  for (int i = tid; i < 1024; i += 256) s_w[i] = wt[i];
  __syncthreads();
  int bb = tid >> 5, o = tid & 31;
  float2 acc = make_float2(0.f, 0.f);
  #pragma unroll 8
  for (int i = 0; i < 32; i++) cfma(acc, s_in[bb*32 + i], s_w[i*32 + o]);
  g_modes2[(size_t)(bb*32 + o)*NMODE + m] = acc;
}

// ---- fused inverse X+Y: modes2[b,o] -> ft1[b,o,x,y,k], no ft2 round-trip ----
// dynamic shared: s_m[4608] | stw[1536] | ftcol[192]  (50688 B)
__global__ void __launch_bounds__(512) k_invXY(){
  extern __shared__ float2 dyn[];
  float2* s_m   = dyn;            // 4608
  float2* stw   = dyn + 4608;     // 1536
  float2* ftcol = dyn + 6144;     // 192
  int bo = blockIdx.x >> 1;
  int x0 = (blockIdx.x & 1) * 32;
  int tid = threadIdx.x;
  for (int i = tid; i < NMODE; i += 512) s_m[i] = g_modes2[(size_t)bo*NMODE + i];
  for (int i = tid; i < NK*64; i += 512) stw[i] = g_tw_yx[i];
  __syncthreads();
  int y = tid >> 3, k = tid & 7;
  for (int x = x0; x < x0 + 32; x++){
    // phase A: ft-column over j2,k (192 threads); twiddle is block-uniform
    if (tid < 192){
      float2 acc = make_float2(0.f, 0.f);
      #pragma unroll
      for (int j1 = 0; j1 < NK; j1++) cfma_cj(acc, s_m[j1*192 + tid], stw[j1*64 + x]);
      ftcol[tid] = acc;
    }
    __syncthreads();
    // phase B: inverse over Y for this x (512 threads)
    {
      float2 acc = make_float2(0.f, 0.f);
      #pragma unroll 4
      for (int j2 = 0; j2 < NK; j2++) cfma_cj(acc, ftcol[j2*8 + k], stw[j2*64 + y]);
      g_ft1[((size_t)bo*64 + x)*512 + tid] = acc;
    }
    __syncthreads();
  }
}

// ---- inverse over T (+scale+Re) + conv1x1 + bias + optional gelu ----
__global__ void __launch_bounds__(256) k_invT_pw(int dir, const float* __restrict__ convw,
                          const float* __restrict__ convb, int act){
  __shared__ float  s_v[2*32*40];
  __shared__ float  s_w[32*33];
  __shared__ float2 s_h[2*32*9];
  __shared__ float2 s_itw[NKZ*NT];
  __shared__ float  s_b[NW];
  const float* vin  = dir ? g_bufB : g_bufA;
  float*       vout = dir ? g_bufA : g_bufB;
  int gx  = blockIdx.x;
  int bb  = gx >> 11;
  int xy0 = (gx & 2047) * 2;
  int tid = threadIdx.x;
  size_t base = (size_t)(bb*32)*XYT + (size_t)xy0*NT;

  for (int idx = tid; idx < 640; idx += 256){
    int c = idx / 20, m = idx % 20;
    float4 v4 = *(const float4*)(vin + base + (size_t)c*XYT + m*4);
    int hh = m / 10, mm = m % 10;
    *(float4*)&s_v[hh*1280 + c*40 + mm*4] = v4;
  }
  for (int idx = tid; idx < 512; idx += 256){
    int hh = idx >> 8, rem = idx & 255, o = rem >> 3, k = rem & 7;
    s_h[hh*288 + o*9 + k] = g_ft1[(size_t)(bb*32+o)*32768 + (size_t)(xy0+hh)*8 + k];
  }
  for (int i = tid; i < 1024; i += 256) s_w[(i>>5)*33 + (i&31)] = convw[i];
  for (int i = tid; i < NKZ*NT; i += 256) s_itw[i] = g_itw_t[i];
  if (tid < NW) s_b[tid] = convb[tid];
  __syncthreads();

  int half = tid >> 7, r = tid & 127;
  int o0 = (r >> 3) * 2, t0 = (r & 7) * 5;
  float acc0[5], acc1[5];
  {
    float b0 = s_b[o0], b1 = s_b[o0+1];
    #pragma unroll
    for (int j = 0; j < 5; j++){ acc0[j] = b0; acc1[j] = b1; }
  }
  {
    float2 h0[8], h1[8];
    #pragma unroll
    for (int k = 0; k < 8; k++){
      h0[k] = s_h[half*288 + o0*9 + k];
      h1[k] = s_h[half*288 + (o0+1)*9 + k];
    }
    #pragma unroll
    for (int k = 0; k < 8; k++){
      #pragma unroll
      for (int j = 0; j < 5; j++){
        float2 tw = s_itw[k*NT + t0 + j];
        acc0[j] = fmaf(h0[k].x, tw.x, fmaf(-h0[k].y, tw.y, acc0[j]));
        acc1[j] = fmaf(h1[k].x, tw.x, fmaf(-h1[k].y, tw.y, acc1[j]));
      }
    }
  }
  {
    float w0[32], w1[32];
    #pragma unroll
    for (int i = 0; i < 32; i++){ w0[i] = s_w[o0*33 + i]; w1[i] = s_w[(o0+1)*33 + i]; }
    const float* vh = s_v + half*1280;
    #pragma unroll 8
    for (int i = 0; i < 32; i++){
      float vj[5];
      #pragma unroll
      for (int j = 0; j < 5; j++) vj[j] = vh[i*40 + t0 + j];
      #pragma unroll
      for (int j = 0; j < 5; j++){
        acc0[j] = fmaf(w0[i], vj[j], acc0[j]);
        acc1[j] = fmaf(w1[i], vj[j], acc1[j]);
      }
    }
  }
  if (act){
    #pragma unroll
    for (int j = 0; j < 5; j++){ acc0[j] = gelu_f(acc0[j]); acc1[j] = gelu_f(acc1[j]); }
  }
  __syncthreads();
  {
    float* ov = s_v + half*1280;
    #pragma unroll
    for (int j = 0; j < 5; j++){ ov[o0*40 + t0 + j] = acc0[j]; ov[(o0+1)*40 + t0 + j] = acc1[j]; }
  }
  __syncthreads();
  for (int idx = tid; idx < 640; idx += 256){
    int c = idx / 20, m = idx % 20;
    int hh = m / 10, mm = m % 10;
    float4 v4 = *(const float4*)&s_v[hh*1280 + c*40 + mm*4];
    *(float4*)(vout + base + (size_t)c*XYT + m*4) = v4;
  }
}

// ---- head: fc1 (gelu) + fc2; j-blocked by 4 with float4 w1 loads ----
__global__ void __launch_bounds__(256) k_head(const float* __restrict__ w1, const float* __restrict__ b1,
                       const float* __restrict__ w2, const float* __restrict__ b2,
                       float* __restrict__ out){
  __shared__ __align__(16) float s_w1[2048];
  __shared__ float s_b1[64];
  __shared__ __align__(16) float s_w2[128];
  __shared__ float s_b2[2];
  int tid = threadIdx.x;
  for (int i = tid; i < 2048; i += 256) s_w1[i] = w1[i];
  if (tid < 64)  s_b1[tid] = b1[tid];
  if (tid < 128) s_w2[tid] = w2[tid];
  if (tid < 2)   s_b2[tid] = b2[tid];
  __syncthreads();
  if (tid >= 240) return;
  int xy_l = tid / 20, tp = tid % 20;        // thread covers t=2*tp, 2*tp+1
  int g = blockIdx.x * 12 + xy_l;
  if (g >= 32768) return;
  int bb = g >> 12, xy = g & 4095;
  float2 vreg[32];
  const float* vb = g_bufB + (size_t)(bb*32)*XYT + (size_t)xy*NT + tp*2;
  #pragma unroll
  for (int c = 0; c < 32; c++) vreg[c] = *(const float2*)(vb + (size_t)c*XYT);
  float o00 = s_b2[0], o01 = s_b2[1], o10 = s_b2[0], o11 = s_b2[1];
  const float4* w1v = (const float4*)s_w1;   // [c*16 + j/4]
  for (int j = 0; j < 64; j += 4){
    float4 b4 = *(const float4*)(s_b1 + j);
    float h0a = b4.x, h0b = b4.y, h0c = b4.z, h0d = b4.w;
    float h1a = b4.x, h1b = b4.y, h1c = b4.z, h1d = b4.w;
    int jq = j >> 2;
    #pragma unroll 8
    for (int c = 0; c < 32; c++){
      float4 w = w1v[c*16 + jq];
      float vx = vreg[c].x, vy = vreg[c].y;
      h0a = fmaf(vx, w.x, h0a); h1a = fmaf(vy, w.x, h1a);
      h0b = fmaf(vx, w.y, h0b); h1b = fmaf(vy, w.y, h1b);
      h0c = fmaf(vx, w.z, h0c); h1c = fmaf(vy, w.z, h1c);
      h0d = fmaf(vx, w.w, h0d); h1d = fmaf(vy, w.w, h1d);
    }
    float g0a = gelu_f(h0a), g0b = gelu_f(h0b), g0c = gelu_f(h0c), g0d = gelu_f(h0d);
    float g1a = gelu_f(h1a), g1b = gelu_f(h1b), g1c = gelu_f(h1c), g1d = gelu_f(h1d);
    float4 wA = *(const float4*)(s_w2 + 2*j);       // w2 for j, j+1
    float4 wB = *(const float4*)(s_w2 + 2*j + 4);   // w2 for j+2, j+3
    o00 = fmaf(g0a, wA.x, o00); o01 = fmaf(g0a, wA.y, o01);
    o10 = fmaf(g1a, wA.x, o10); o11 = fmaf(g1a, wA.y, o11);
    o00 = fmaf(g0b, wA.z, o00); o01 = fmaf(g0b, wA.w, o01);
    o10 = fmaf(g1b, wA.z, o10); o11 = fmaf(g1b, wA.w, o11);
    o00 = fmaf(g0c, wB.x, o00); o01 = fmaf(g0c, wB.y, o01);
    o10 = fmaf(g1c, wB.x, o10); o11 = fmaf(g1c, wB.y, o11);
    o00 = fmaf(g0d, wB.z, o00); o01 = fmaf(g0d, wB.w, o01);
    o10 = fmaf(g1d, wB.z, o10); o11 = fmaf(g1d, wB.w, o11);
  }
  float4 res = make_float4(o00, o01, o10, o11);
  *(float4*)(out + (size_t)g*80 + tp*4) = res;
}

#define INVXY_SMEM 50688

extern "C" void kernel_launch(void* const* d_in, const int* in_sizes, int n_in,
                              void* d_out, int out_size){
  (void)in_sizes; (void)n_in; (void)out_size;
  const float* h     = (const float*)d_in[0];
  const float* xin   = (const float*)d_in[1];
  const float* fc0_w = (const float*)d_in[2];
  const float* fc0_b = (const float*)d_in[3];
  const float* scr[3] = {(const float*)d_in[4], (const float*)d_in[6], (const float*)d_in[8]};
  const float* sci[3] = {(const float*)d_in[5], (const float*)d_in[7], (const float*)d_in[9]};
  const float* cw[3]  = {(const float*)d_in[10], (const float*)d_in[12], (const float*)d_in[14]};
  const float* cb[3]  = {(const float*)d_in[11], (const float*)d_in[13], (const float*)d_in[15]};
  const float* fc1_w = (const float*)d_in[16];
  const float* fc1_b = (const float*)d_in[17];
  const float* fc2_w = (const float*)d_in[18];
  const float* fc2_b = (const float*)d_in[19];
  float* out = (float*)d_out;

  cudaFuncSetAttribute(k_invXY, cudaFuncAttributeMaxDynamicSharedMemorySize, INVXY_SMEM);

  dim3 pgrid(36, 32, 4);

  k_init_tw<<<1, 256>>>();                              // 0
  k_fc0<<<(NB*XYT)/256, 256>>>(h, xin, fc0_w, fc0_b);   // 1
  k_fwdT_r<<<NB*NW*NX/2, 128>>>(0);                     // 2
  k_fwdY<<<NB*NW*NX/8, 384>>>();                        // 3  <- profiled
  k_prep_w_t<<<pgrid, 256>>>(scr[0], sci[0], 0);
  k_fwdX<<<NB*NW*4, 192>>>();
  k_mix<<<NMODE, 256>>>(0);
  k_invXY<<<NB*NW*2, 512, INVXY_SMEM>>>();
  k_invT_pw<<<NB*2048, 256>>>(0, cw[0], cb[0], 1);      // A->B, gelu

  k_fwdT_r<<<NB*NW*NX/2, 128>>>(1);
  k_fwdY<<<NB*NW*NX/8, 384>>>();
  k_prep_w_t<<<pgrid, 256>>>(scr[1], sci[1], 1);
  k_fwdX<<<NB*NW*4, 192>>>();
  k_mix<<<NMODE, 256>>>(1);
  k_invXY<<<NB*NW*2, 512, INVXY_SMEM>>>();
  k_invT_pw<<<NB*2048, 256>>>(1, cw[1], cb[1], 1);      // B->A, gelu

  k_fwdT_r<<<NB*NW*NX/2, 128>>>(0);
  k_fwdY<<<NB*NW*NX/8, 384>>>();
  k_prep_w_t<<<pgrid, 256>>>(scr[2], sci[2], 2);
  k_fwdX<<<NB*NW*4, 192>>>();
  k_mix<<<NMODE, 256>>>(2);
  k_invXY<<<NB*NW*2, 512, INVXY_SMEM>>>();
  k_invT_pw<<<NB*2048, 256>>>(0, cw[2], cb[2], 0);      // A->B, no act

  k_head<<<(32768 + 11)/12, 256>>>(fc1_w, fc1_b, fc2_w, fc2_b, out);
}

// round 17
// speedup vs baseline: 1.2199x; 1.2199x over previous
#include <cuda_runtime.h>
#include <cstdint>

// Problem constants
#define NB 8
#define NW 32
#define NX 64
#define NY 64
#define NT 40
#define NKZ 8          // retained T modes (M3)
#define NK 24          // retained X/Y modes (2*M1 = 2*M2)
#define XYT 163840     // 64*64*40
#define YTD 2560       // 64*40
#define NMODE 4608     // 24*24*8
#define WPL 4718592    // 4*32*32*12*12*8  (spectral weights per layer)

// ---- scratch (device globals; no allocations anywhere) ----
static __device__ float  g_bufA[(size_t)NB*NW*XYT];                 // 168 MB
static __device__ float  g_bufB[(size_t)NB*NW*XYT];                 // 168 MB
static __device__ float2 g_ft1[(size_t)NB*NW*NX*NY*NKZ];            // 67 MB
static __device__ float2 g_ft2[(size_t)NB*NW*NX*NK*NKZ];            // 25 MB
static __device__ float2 g_modes [(size_t)NB*NW*NMODE];             // 9.4 MB
static __device__ float2 g_modes2[(size_t)NB*NW*NMODE];             // 9.4 MB
static __device__ float2 g_wt[(size_t)3*WPL];                       // 113 MB
static __device__ float2 g_tw_t[NKZ*NT];    // forward T twiddles  e^{-2pi i k t/40}
static __device__ float2 g_itw_t[NKZ*NT];   // inverse T twiddles  c_k/(XYT) * e^{+2pi i k t/40}
static __device__ float2 g_tw_yx[NK*64];    // forward X/Y twiddles e^{-2pi i kv y/64}

__device__ __forceinline__ void cfma(float2& a, float2 b, float2 c){
  a.x = fmaf(b.x, c.x, fmaf(-b.y, c.y, a.x));
  a.y = fmaf(b.x, c.y, fmaf( b.y, c.x, a.y));
}
__device__ __forceinline__ void cfma_cj(float2& a, float2 b, float2 c){ // a += b*conj(c)
  a.x = fmaf(b.x, c.x, fmaf( b.y, c.y, a.x));
  a.y = fmaf(b.y, c.x, fmaf(-b.x, c.y, a.y));
}
__device__ __forceinline__ float gelu_f(float z){
  return 0.5f*z*(1.0f + erff(z*0.7071067811865476f));
}

// ---- twiddle tables ----
__global__ void k_init_tw(){
  int tid = threadIdx.x;
  for (int i = tid; i < NKZ*NT; i += blockDim.x){
    int k = i / NT, t = i % NT;
    float s, c; sincospif(-(float)(k*t)/20.0f, &s, &c);   // -2pi k t / 40
    g_tw_t[i] = make_float2(c, s);
    float sc = ((k==0) ? 1.0f : 2.0f) * (1.0f/163840.0f);
    float s2, c2; sincospif((float)(k*t)/20.0f, &s2, &c2);
    g_itw_t[i] = make_float2(sc*c2, sc*s2);
  }
  for (int i = tid; i < NK*64; i += blockDim.x){
    int j = i / 64, y = i % 64;
    int kv = (j < 12) ? j : j + 40;                        // 0..11, 52..63
    float s, c; sincospif(-(float)(kv*y)/32.0f, &s, &c);   // -2pi kv y / 64
    g_tw_yx[i] = make_float2(c, s);
  }
}

// ---- transpose spectral weights via 32x32 shared tile ----
__global__ void __launch_bounds__(256) k_prep_w_t(const float* __restrict__ wr,
                                                  const float* __restrict__ wi, int L){
  __shared__ float2 s[32][33];
  int m0  = blockIdx.x * 32;
  int io0 = blockIdx.y * 32;
  int r   = blockIdx.z;
  int tid = threadIdx.x;
  {
    int mt = tid & 31, iot0 = tid >> 5;
    const size_t inbase = (size_t)r * 1024 * 1152;
    #pragma unroll
    for (int u = 0; u < 4; u++){
      int io = io0 + iot0 + u*8;
      size_t off = inbase + (size_t)io*1152 + m0 + mt;
      s[iot0 + u*8][mt] = make_float2(wr[off], wi[off]);
    }
  }
  __syncthreads();
  {
    int iot = tid & 31, mt0 = tid >> 5;
    int rbase = (r & 1) * 2304 + ((r >> 1) & 1) * 96;
    float2* dst = g_wt + (size_t)L*WPL;
    #pragma unroll
    for (int u = 0; u < 4; u++){
      int m  = m0 + mt0 + u*8;
      int m1 = m / 96, rem = m % 96;
      int mode = rbase + m1*192 + rem;
      dst[(size_t)mode*1024 + io0 + iot] = s[iot][mt0 + u*8];
    }
  }
}

// ---- fc0: lift [B,X,Y,T,5] -> v [B,W,X,Y,T] ----
__global__ void k_fc0(const float* __restrict__ h, const float* __restrict__ xin,
                      const float* __restrict__ w, const float* __restrict__ b){
  int p = blockIdx.x * blockDim.x + threadIdx.x;
  if (p >= NB*XYT) return;
  int bb = p / XYT, rem = p % XYT;
  float in5[5];
  in5[0] = h[(size_t)p*2];   in5[1] = h[(size_t)p*2+1];
  in5[2] = xin[(size_t)p*3]; in5[3] = xin[(size_t)p*3+1]; in5[4] = xin[(size_t)p*3+2];
  float* o = g_bufA + (size_t)bb*NW*XYT + rem;
  #pragma unroll 4
  for (int c = 0; c < NW; c++){
    float v = b[c];
    #pragma unroll
    for (int f = 0; f < 5; f++) v = fmaf(in5[f], w[f*NW + c], v);
    o[(size_t)c*XYT] = v;
  }
}

// ---- forward partial DFT over T, radix 8x5 ----
__global__ void __launch_bounds__(128) k_fwdT_r(int dir){
  __shared__ float  s[2*NY*41];
  __shared__ float2 stw40[NT];
  const float* vin = dir ? g_bufB : g_bufA;
  int bcx0 = blockIdx.x * 2;
  const float* src = vin + (size_t)bcx0*YTD;
  int tid = threadIdx.x;
  for (int i = tid; i < 2*YTD; i += 128){
    int sl = i / YTD, r = i % YTD;
    s[sl*2624 + (r/NT)*41 + (r%NT)] = src[i];
  }
  if (tid < NT) stw40[tid] = g_tw_t[40 + tid];
  __syncthreads();
  int sl = tid >> 6, y = tid & 63;
  const float* row = s + sl*2624 + y*41;
  const float C = 0.70710678118654752f;
  float g0[5], g4[5], g1r[5], g1i[5], g2r[5], g2i[5], g3r[5], g3i[5];
  #pragma unroll
  for (int b = 0; b < 5; b++){
    float a0 = row[b], a1 = row[5+b], a2 = row[10+b], a3 = row[15+b];
    float a4 = row[20+b], a5 = row[25+b], a6 = row[30+b], a7 = row[35+b];
    float s0 = a0+a4, s1 = a1+a5, s2 = a2+a6, s3 = a3+a7;
    float d0 = a0-a4, d1 = a1-a5, d2 = a2-a6, d3 = a3-a7;
    g0[b] = (s0+s2) + (s1+s3);
    g4[b] = (s0+s2) - (s1+s3);
    g2r[b] = s0-s2;  g2i[b] = s3-s1;
    float t1 = C*(d1-d3), t2 = C*(d1+d3);
    g1r[b] = d0+t1;  g1i[b] = -d2 - t2;
    g3r[b] = d0-t1;  g3i[b] =  d2 - t2;
  }
  float Xr[8], Xi[8];
  Xr[0] = g0[0]+g0[1]+g0[2]+g0[3]+g0[4];  Xi[0] = 0.f;
  #pragma unroll
  for (int k = 1; k < 8; k++){ Xr[k] = 0.f; Xi[k] = 0.f; }
  #pragma unroll
  for (int b = 0; b < 5; b++){
    float2 tw;
    tw = stw40[1*b];
    Xr[1] = fmaf(tw.x, g1r[b], fmaf(-tw.y, g1i[b], Xr[1]));
    Xi[1] = fmaf(tw.x, g1i[b], fmaf( tw.y, g1r[b], Xi[1]));
    tw = stw40[2*b];
    Xr[2] = fmaf(tw.x, g2r[b], fmaf(-tw.y, g2i[b], Xr[2]));
    Xi[2] = fmaf(tw.x, g2i[b], fmaf( tw.y, g2r[b], Xi[2]));
    tw = stw40[3*b];
    Xr[3] = fmaf(tw.x, g3r[b], fmaf(-tw.y, g3i[b], Xr[3]));
    Xi[3] = fmaf(tw.x, g3i[b], fmaf( tw.y, g3r[b], Xi[3]));
    tw = stw40[4*b];
    Xr[4] = fmaf(tw.x, g4[b], Xr[4]);
    Xi[4] = fmaf(tw.y, g4[b], Xi[4]);
    tw = stw40[5*b];
    Xr[5] = fmaf(tw.x, g3r[b], fmaf( tw.y, g3i[b], Xr[5]));
    Xi[5] = fmaf(tw.x, -g3i[b], fmaf( tw.y, g3r[b], Xi[5]));
    tw = stw40[6*b];
    Xr[6] = fmaf(tw.x, g2r[b], fmaf( tw.y, g2i[b], Xr[6]));
    Xi[6] = fmaf(tw.x, -g2i[b], fmaf( tw.y, g2r[b], Xi[6]));
    tw = stw40[7*b];
    Xr[7] = fmaf(tw.x, g1r[b], fmaf( tw.y, g1i[b], Xr[7]));
    Xi[7] = fmaf(tw.x, -g1i[b], fmaf( tw.y, g1r[b], Xi[7]));
  }
  float2* dst = g_ft1 + ((size_t)(bcx0+sl)*NY + y)*NKZ;
  #pragma unroll
  for (int k = 0; k < NKZ; k++) dst[k] = make_float2(Xr[k], Xi[k]);
}

// ---- forward partial DFT over Y: warp-broadcast twiddles, 8 slices, 384 thr ----
__global__ void __launch_bounds__(384) k_fwdY(){
  __shared__ float2 sv[8*512];      // 32 KB  [s][y*8+k]
  __shared__ float2 stw[NK*64];     // 12 KB
  int bcx0 = blockIdx.x * 8;
  int tid = threadIdx.x;
  for (int i = tid; i < 4096; i += 384) sv[i] = g_ft1[(size_t)bcx0*512 + i];
  for (int i = tid; i < NK*64; i += 384) stw[i] = g_tw_yx[i];
  __syncthreads();
  int w = tid >> 5;                  // 12 warps
  int wj = w % 6;                    // j-group of 4
  int half = w / 6;                  // slice half
  int lane = tid & 31;
  int s = half*4 + (lane >> 3), k = lane & 7;
  const float2* svp = sv + s*512 + k;
  const float2* twp = stw + wj*256;
  float2 a0 = make_float2(0.f,0.f), a1 = a0, a2 = a0, a3 = a0;
  #pragma unroll 4
  for (int y = 0; y < 64; y++){
    float2 v = svp[y*8];
    cfma(a0, v, twp[y]);
    cfma(a1, v, twp[64 + y]);
    cfma(a2, v, twp[128 + y]);
    cfma(a3, v, twp[192 + y]);
  }
  float2* dst = g_ft2 + (size_t)(bcx0 + s)*192 + k;
  dst[(wj*4 + 0)*8] = a0;
  dst[(wj*4 + 1)*8] = a1;
  dst[(wj*4 + 2)*8] = a2;
  dst[(wj*4 + 3)*8] = a3;
}

// ---- forward partial DFT over X: stream x once, 6 j1 per block ----
__global__ void __launch_bounds__(192) k_fwdX(){
  __shared__ float2 stw[6*64];
  int bc = blockIdx.x >> 2;
  int jg = (blockIdx.x & 3) * 6;
  int tid = threadIdx.x;
  for (int i = tid; i < 6*64; i += 192) stw[i] = g_tw_yx[jg*64 + i];
  __syncthreads();
  const float2* src = g_ft2 + (size_t)bc*NX*192 + tid;
  float2 acc[6];
  #pragma unroll
  for (int j = 0; j < 6; j++) acc[j] = make_float2(0.f, 0.f);
  #pragma unroll 4
  for (int x = 0; x < 64; x++){
    float2 v = src[(size_t)x*192];
    #pragma unroll
    for (int j = 0; j < 6; j++) cfma(acc[j], v, stw[j*64 + x]);
  }
  float2* dst = g_modes + (size_t)bc*NMODE + (size_t)jg*192 + tid;
  #pragma unroll
  for (int j = 0; j < 6; j++) dst[(size_t)j*192] = acc[j];
}

// ---- channel mix per mode ----
__global__ void k_mix(int L){
  __shared__ float2 s_in[256];
  __shared__ float2 s_w[1024];
  int m = blockIdx.x;
  int tid = threadIdx.x;
  s_in[tid] = g_modes[(size_t)tid*NMODE + m];
  const float2* wt = g_wt + (size_t)L*WPL + (size_t)m*1024;
  for (int i = tid; i < 1024; i += 256) s_w[i] = wt[i];
  __syncthreads();
  int bb = tid >> 5, o = tid & 31;
  float2 acc = make_float2(0.f, 0.f);
  #pragma unroll 8
  for (int i = 0; i < 32; i++) cfma(acc, s_in[bb*32 + i], s_w[i*32 + o]);
  g_modes2[(size_t)(bb*32 + o)*NMODE + m] = acc;
}

// ---- inverse over X: x-split x4 for occupancy ----
__global__ void k_invX(){
  __shared__ float2 stw[NK*64];
  int bo = blockIdx.x >> 2;
  int xs = (blockIdx.x & 3) * 16;
  int tid = threadIdx.x;
  for (int i = tid; i < NK*64; i += 192) stw[i] = g_tw_yx[i];
  float2 m[NK];
  #pragma unroll
  for (int j1 = 0; j1 < NK; j1++)
    m[j1] = g_modes2[(size_t)bo*NMODE + j1*192 + tid];
  __syncthreads();
  #pragma unroll 4
  for (int x = xs; x < xs + 16; x++){
    float2 acc = make_float2(0.f, 0.f);
    #pragma unroll
    for (int j1 = 0; j1 < NK; j1++) cfma_cj(acc, m[j1], stw[j1*64 + x]);
    g_ft2[((size_t)bo*64 + x)*192 + tid] = acc;
  }
}

// ---- inverse over Y: warp-broadcast twiddles, 4 slices/block ----
__global__ void __launch_bounds__(256) k_invY(){
  __shared__ float2 s_in[4*192];
  __shared__ float2 stw[NK*64];
  int box0 = blockIdx.x * 4;
  int tid = threadIdx.x;
  for (int i = tid; i < 768; i += 256) s_in[i] = g_ft2[(size_t)box0*192 + i];
  for (int i = tid; i < NK*64; i += 256) stw[i] = g_tw_yx[i];
  __syncthreads();
  int w = tid >> 5;
  int lane = tid & 31;
  int s = lane >> 3, k = lane & 7;
  const float2* ip = s_in + s*192 + k;
  const float2* twp = stw + w*8;
  float2 acc[8];
  #pragma unroll
  for (int u = 0; u < 8; u++) acc[u] = make_float2(0.f, 0.f);
  #pragma unroll 4
  for (int j2 = 0; j2 < NK; j2++){
    float2 v = ip[j2*8];
    const float2* tw = twp + j2*64;
    #pragma unroll
    for (int u = 0; u < 8; u++) cfma_cj(acc[u], v, tw[u]);
  }
  float2* dst = g_ft1 + (size_t)(box0 + s)*512 + w*64 + k;
  #pragma unroll
  for (int u = 0; u < 8; u++) dst[u*8] = acc[u];
}

// ---- inverse over T (+scale+Re) + conv1x1 + bias + optional gelu ----
// 320 threads, 2 xy per block; thread tile 2-o x 4-t -> all inner accesses 16B-aligned.
__global__ void __launch_bounds__(320) k_invT_pw(int dir, const float* __restrict__ convw,
                          const float* __restrict__ convb, int act){
  __shared__ __align__(16) float  s_v[2*32*40];   // 10 KB
  __shared__ float  s_w[32*33];                    // 4.2 KB (padded)
  __shared__ float2 s_h[2*32*9];                   // 4.6 KB (padded)
  __shared__ __align__(16) float2 s_itw[NKZ*NT];   // 2.5 KB
  __shared__ float  s_b[NW];
  const float* vin  = dir ? g_bufB : g_bufA;
  float*       vout = dir ? g_bufA : g_bufB;
  int gx  = blockIdx.x;
  int bb  = gx >> 11;
  int xy0 = (gx & 2047) * 2;
  int tid = threadIdx.x;
  size_t base = (size_t)(bb*32)*XYT + (size_t)xy0*NT;

  for (int idx = tid; idx < 640; idx += 320){
    int c = idx / 20, m = idx % 20;
    float4 v4 = *(const float4*)(vin + base + (size_t)c*XYT + m*4);
    int hh = m / 10, mm = m % 10;
    *(float4*)&s_v[hh*1280 + c*40 + mm*4] = v4;
  }
  for (int idx = tid; idx < 512; idx += 320){
    int hh = idx >> 8, rem = idx & 255, o = rem >> 3, k = rem & 7;
    s_h[hh*288 + o*9 + k] = g_ft1[(size_t)(bb*32+o)*32768 + (size_t)(xy0+hh)*8 + k];
  }
  for (int i = tid; i < 1024; i += 320) s_w[(i>>5)*33 + (i&31)] = convw[i];
  for (int i = tid; i < NKZ*NT; i += 320) s_itw[i] = g_itw_t[i];
  if (tid < NW) s_b[tid] = convb[tid];
  __syncthreads();

  int half = tid >= 160, r = tid - half*160;
  int o0 = (r / 10) * 2, t0 = (r % 10) * 4;
  float acc0[4], acc1[4];
  {
    float b0 = s_b[o0], b1 = s_b[o0+1];
    #pragma unroll
    for (int j = 0; j < 4; j++){ acc0[j] = b0; acc1[j] = b1; }
  }
  // idft-T: vectorized twiddle loads (2x LDS.128 per k), h from shared
  {
    const float2* hp0 = s_h + half*288 + o0*9;
    const float2* hp1 = hp0 + 9;
    #pragma unroll
    for (int k = 0; k < NKZ; k++){
      float2 h0 = hp0[k], h1 = hp1[k];
      float4 twa = *(const float4*)&s_itw[k*NT + t0];       // j=0,1
      float4 twb = *(const float4*)&s_itw[k*NT + t0 + 2];   // j=2,3
      acc0[0] = fmaf(h0.x, twa.x, fmaf(-h0.y, twa.y, acc0[0]));
      acc1[0] = fmaf(h1.x, twa.x, fmaf(-h1.y, twa.y, acc1[0]));
      acc0[1] = fmaf(h0.x, twa.z, fmaf(-h0.y, twa.w, acc0[1]));
      acc1[1] = fmaf(h1.x, twa.z, fmaf(-h1.y, twa.w, acc1[1]));
      acc0[2] = fmaf(h0.x, twb.x, fmaf(-h0.y, twb.y, acc0[2]));
      acc1[2] = fmaf(h1.x, twb.x, fmaf(-h1.y, twb.y, acc1[2]));
      acc0[3] = fmaf(h0.x, twb.z, fmaf(-h0.y, twb.w, acc0[3]));
      acc1[3] = fmaf(h1.x, twb.z, fmaf(-h1.y, twb.w, acc1[3]));
    }
  }
  // conv1x1: one LDS.128 per i for v; weights near-broadcast from shared
  {
    const float* vh = s_v + half*1280;
    const float* wr0 = s_w + o0*33;
    const float* wr1 = s_w + (o0+1)*33;
    #pragma unroll 8
    for (int i = 0; i < 32; i++){
      float4 v4 = *(const float4*)(vh + i*40 + t0);
      float w0 = wr0[i], w1 = wr1[i];
      acc0[0] = fmaf(w0, v4.x, acc0[0]); acc1[0] = fmaf(w1, v4.x, acc1[0]);
      acc0[1] = fmaf(w0, v4.y, acc0[1]); acc1[1] = fmaf(w1, v4.y, acc1[1]);
      acc0[2] = fmaf(w0, v4.z, acc0[2]); acc1[2] = fmaf(w1, v4.z, acc1[2]);
      acc0[3] = fmaf(w0, v4.w, acc0[3]); acc1[3] = fmaf(w1, v4.w, acc1[3]);
    }
  }
  if (act){
    #pragma unroll
    for (int j = 0; j < 4; j++){ acc0[j] = gelu_f(acc0[j]); acc1[j] = gelu_f(acc1[j]); }
  }
  __syncthreads();           // all reads of s_v done
  {
    float* ov = s_v + half*1280;
    *(float4*)&ov[o0*40 + t0]     = make_float4(acc0[0], acc0[1], acc0[2], acc0[3]);
    *(float4*)&ov[(o0+1)*40 + t0] = make_float4(acc1[0], acc1[1], acc1[2], acc1[3]);
  }
  __syncthreads();
  for (int idx = tid; idx < 640; idx += 320){
    int c = idx / 20, m = idx % 20;
    int hh = m / 10, mm = m % 10;
    float4 v4 = *(const float4*)&s_v[hh*1280 + c*40 + mm*4];
    *(float4*)(vout + base + (size_t)c*XYT + m*4) = v4;
  }
}

// ---- head: fc1 (gelu) + fc2; j-blocked by 4 with float4 w1 loads ----
__global__ void __launch_bounds__(256) k_head(const float* __restrict__ w1, const float* __restrict__ b1,
                       const float* __restrict__ w2, const float* __restrict__ b2,
                       float* __restrict__ out){
  __shared__ __align__(16) float s_w1[2048];
  __shared__ float s_b1[64];
  __shared__ __align__(16) float s_w2[128];
  __shared__ float s_b2[2];
  int tid = threadIdx.x;
  for (int i = tid; i < 2048; i += 256) s_w1[i] = w1[i];
  if (tid < 64)  s_b1[tid] = b1[tid];
  if (tid < 128) s_w2[tid] = w2[tid];
  if (tid < 2)   s_b2[tid] = b2[tid];
  __syncthreads();
  if (tid >= 240) return;
  int xy_l = tid / 20, tp = tid % 20;        // thread covers t=2*tp, 2*tp+1
  int g = blockIdx.x * 12 + xy_l;
  if (g >= 32768) return;
  int bb = g >> 12, xy = g & 4095;
  float2 vreg[32];
  const float* vb = g_bufB + (size_t)(bb*32)*XYT + (size_t)xy*NT + tp*2;
  #pragma unroll
  for (int c = 0; c < 32; c++) vreg[c] = *(const float2*)(vb + (size_t)c*XYT);
  float o00 = s_b2[0], o01 = s_b2[1], o10 = s_b2[0], o11 = s_b2[1];
  const float4* w1v = (const float4*)s_w1;   // [c*16 + j/4]
  for (int j = 0; j < 64; j += 4){
    float4 b4 = *(const float4*)(s_b1 + j);
    float h0a = b4.x, h0b = b4.y, h0c = b4.z, h0d = b4.w;
    float h1a = b4.x, h1b = b4.y, h1c = b4.z, h1d = b4.w;
    int jq = j >> 2;
    #pragma unroll 8
    for (int c = 0; c < 32; c++){
      float4 w = w1v[c*16 + jq];
      float vx = vreg[c].x, vy = vreg[c].y;
      h0a = fmaf(vx, w.x, h0a); h1a = fmaf(vy, w.x, h1a);
      h0b = fmaf(vx, w.y, h0b); h1b = fmaf(vy, w.y, h1b);
      h0c = fmaf(vx, w.z, h0c); h1c = fmaf(vy, w.z, h1c);
      h0d = fmaf(vx, w.w, h0d); h1d = fmaf(vy, w.w, h1d);
    }
    float g0a = gelu_f(h0a), g0b = gelu_f(h0b), g0c = gelu_f(h0c), g0d = gelu_f(h0d);
    float g1a = gelu_f(h1a), g1b = gelu_f(h1b), g1c = gelu_f(h1c), g1d = gelu_f(h1d);
    float4 wA = *(const float4*)(s_w2 + 2*j);       // w2 for j, j+1
    float4 wB = *(const float4*)(s_w2 + 2*j + 4);   // w2 for j+2, j+3
    o00 = fmaf(g0a, wA.x, o00); o01 = fmaf(g0a, wA.y, o01);
    o10 = fmaf(g1a, wA.x, o10); o11 = fmaf(g1a, wA.y, o11);
    o00 = fmaf(g0b, wA.z, o00); o01 = fmaf(g0b, wA.w, o01);
    o10 = fmaf(g1b, wA.z, o10); o11 = fmaf(g1b, wA.w, o11);
    o00 = fmaf(g0c, wB.x, o00); o01 = fmaf(g0c, wB.y, o01);
    o10 = fmaf(g1c, wB.x, o10); o11 = fmaf(g1c, wB.y, o11);
    o00 = fmaf(g0d, wB.z, o00); o01 = fmaf(g0d, wB.w, o01);
    o10 = fmaf(g1d, wB.z, o10); o11 = fmaf(g1d, wB.w, o11);
  }
  float4 res = make_float4(o00, o01, o10, o11);
  *(float4*)(out + (size_t)g*80 + tp*4) = res;
}

extern "C" void kernel_launch(void* const* d_in, const int* in_sizes, int n_in,
                              void* d_out, int out_size){
  (void)in_sizes; (void)n_in; (void)out_size;
  const float* h     = (const float*)d_in[0];
  const float* xin   = (const float*)d_in[1];
  const float* fc0_w = (const float*)d_in[2];
  const float* fc0_b = (const float*)d_in[3];
  const float* scr[3] = {(const float*)d_in[4], (const float*)d_in[6], (const float*)d_in[8]};
  const float* sci[3] = {(const float*)d_in[5], (const float*)d_in[7], (const float*)d_in[9]};
  const float* cw[3]  = {(const float*)d_in[10], (const float*)d_in[12], (const float*)d_in[14]};
  const float* cb[3]  = {(const float*)d_in[11], (const float*)d_in[13], (const float*)d_in[15]};
  const float* fc1_w = (const float*)d_in[16];
  const float* fc1_b = (const float*)d_in[17];
  const float* fc2_w = (const float*)d_in[18];
  const float* fc2_b = (const float*)d_in[19];
  float* out = (float*)d_out;

  dim3 pgrid(36, 32, 4);

  k_init_tw<<<1, 256>>>();                              // 0
  k_fc0<<<(NB*XYT)/256, 256>>>(h, xin, fc0_w, fc0_b);   // 1
  k_fwdT_r<<<NB*NW*NX/2, 128>>>(0);                     // 2
  k_fwdY<<<NB*NW*NX/8, 384>>>();                        // 3  <- profiled
  k_prep_w_t<<<pgrid, 256>>>(scr[0], sci[0], 0);
  k_fwdX<<<NB*NW*4, 192>>>();
  k_mix<<<NMODE, 256>>>(0);
  k_invX<<<NB*NW*4, 192>>>();
  k_invY<<<NB*NW*NX/4, 256>>>();
  k_invT_pw<<<NB*2048, 320>>>(0, cw[0], cb[0], 1);      // A->B, gelu

  k_fwdT_r<<<NB*NW*NX/2, 128>>>(1);
  k_fwdY<<<NB*NW*NX/8, 384>>>();
  k_prep_w_t<<<pgrid, 256>>>(scr[1], sci[1], 1);
  k_fwdX<<<NB*NW*4, 192>>>();
  k_mix<<<NMODE, 256>>>(1);
  k_invX<<<NB*NW*4, 192>>>();
  k_invY<<<NB*NW*NX/4, 256>>>();
  k_invT_pw<<<NB*2048, 320>>>(1, cw[1], cb[1], 1);      // B->A, gelu

  k_fwdT_r<<<NB*NW*NX/2, 128>>>(0);
  k_fwdY<<<NB*NW*NX/8, 384>>>();
  k_prep_w_t<<<pgrid, 256>>>(scr[2], sci[2], 2);
  k_fwdX<<<NB*NW*4, 192>>>();
  k_mix<<<NMODE, 256>>>(2);
  k_invX<<<NB*NW*4, 192>>>();
  k_invY<<<NB*NW*NX/4, 256>>>();
  k_invT_pw<<<NB*2048, 320>>>(0, cw[2], cb[2], 0);      // A->B, no act

  k_head<<<(32768 + 11)/12, 256>>>(fc1_w, fc1_b, fc2_w, fc2_b, out);
}